// round 10
// baseline (speedup 1.0000x reference)
#include <cuda_runtime.h>
#include <cuda_fp16.h>
#include <cstdint>

#define EE 800000
#define NN 50000
#define FULL 0xFFFFFFFFu

#define TE_S 128
#define NBLK_S (EE / TE_S)   // 6250
#define TE_V 128
#define NBLK_V (EE / TE_V)   // 6250

// ---------------- scratch (device globals; no allocation) ----------------
__device__ float g_score[(size_t)EE * 4];   // raw scores
__device__ float g_smax[NN * 4];
__device__ float g_denom[NN * 4];           // segment_sum(ex)
__device__ uint2 g_wfrag[3 * 8 * 4 * 32];   // [mat][n][ks][lane] = {wh0, wh1} fp16

// ---------------- smem layouts (bytes) ----------------
#define XW 36                                 // words per X row (64 fp16 + pad)
#define XTILE (128 * 144)
// score kernel: Xq_h, Xq_l (reused as k_l), Xk_h, Wf(2 mats), bias
#define OFF_XQH 0
#define OFF_XQL (XTILE)
#define OFF_XKH (2 * XTILE)
#define OFF_WF_A (3 * XTILE)
#define OFF_BIAS_A (OFF_WF_A + 2048 * 8)
#define SMEM_A (OFF_BIAS_A + 512)             // 72192 B -> 3 blocks/SM
// value kernel: Xv (fp16 only), Wf(1 mat), bias
#define OFF_XV 0
#define OFF_WF_B (XTILE)
#define OFF_BIAS_B (OFF_WF_B + 1024 * 8)
#define SMEM_B (OFF_BIAS_B + 256)

// ---------------- helpers ----------------
__device__ __forceinline__ uint32_t pack_h2(float a, float b) {
    __half2 h = __floats2half2_rn(a, b);
    return *(uint32_t *)&h;
}

__device__ __forceinline__ void mma_f16(float c[4], const uint32_t a[4],
                                        uint32_t b0, uint32_t b1) {
    asm volatile(
        "mma.sync.aligned.m16n8k16.row.col.f32.f16.f16.f32 "
        "{%0,%1,%2,%3}, {%4,%5,%6,%7}, {%8,%9}, {%0,%1,%2,%3};"
        : "+f"(c[0]), "+f"(c[1]), "+f"(c[2]), "+f"(c[3])
        : "r"(a[0]), "r"(a[1]), "r"(a[2]), "r"(a[3]), "r"(b0), "r"(b1));
}

// stage 128-row X tile -> fp16 hi + lo smem tiles
__device__ __forceinline__ void stageX2(const float *__restrict__ gsrc, long gbase,
                                        uint32_t *Xh, uint32_t *Xl, int tid) {
#pragma unroll
    for (int it = 0; it < 8; it++) {
        int idx = tid + it * 256;            // over 2048 float4
        int row = idx >> 4, c4 = idx & 15;
        float4 x = ((const float4 *)(gsrc + (gbase + row) * 64))[c4];
        float hx = __half2float(__float2half_rn(x.x));
        float hy = __half2float(__float2half_rn(x.y));
        float hz = __half2float(__float2half_rn(x.z));
        float hw = __half2float(__float2half_rn(x.w));
        uint2 wh, wl;
        wh.x = pack_h2(hx, hy);
        wh.y = pack_h2(hz, hw);
        wl.x = pack_h2(x.x - hx, x.y - hy);
        wl.y = pack_h2(x.z - hz, x.w - hw);
        ((uint2 *)(Xh + row * XW))[c4] = wh;
        ((uint2 *)(Xl + row * XW))[c4] = wl;
    }
}

// stage 128-row X tile -> single fp16 (hi) smem tile
__device__ __forceinline__ void stageX1(const float *__restrict__ gsrc, long gbase,
                                        uint32_t *X, int tid) {
#pragma unroll
    for (int it = 0; it < 8; it++) {
        int idx = tid + it * 256;
        int row = idx >> 4, c4 = idx & 15;
        float4 x = ((const float4 *)(gsrc + (gbase + row) * 64))[c4];
        uint2 wrd;
        wrd.x = pack_h2(x.x, x.y);
        wrd.y = pack_h2(x.z, x.w);
        ((uint2 *)(X + row * XW))[c4] = wrd;
    }
}

// re-read X tile (L1/L2 hot) -> fp16 lo residual tile only
__device__ __forceinline__ void stageXlo(const float *__restrict__ gsrc, long gbase,
                                         uint32_t *Xl, int tid) {
#pragma unroll
    for (int it = 0; it < 8; it++) {
        int idx = tid + it * 256;
        int row = idx >> 4, c4 = idx & 15;
        float4 x = ((const float4 *)(gsrc + (gbase + row) * 64))[c4];
        float hx = __half2float(__float2half_rn(x.x));
        float hy = __half2float(__float2half_rn(x.y));
        float hz = __half2float(__float2half_rn(x.z));
        float hw = __half2float(__float2half_rn(x.w));
        uint2 wl;
        wl.x = pack_h2(x.x - hx, x.y - hy);
        wl.y = pack_h2(x.z - hz, x.w - hw);
        ((uint2 *)(Xl + row * XW))[c4] = wl;
    }
}

// 16-edge m-tile projection, 2-term (x hi/lo): acc[8][4]
__device__ __forceinline__ void proj_tile2(const uint32_t *Xh, const uint32_t *Xl,
                                           const uint2 *Wf, int m, int rbase,
                                           int g, int qd, int lane, float acc[8][4]) {
#pragma unroll
    for (int n = 0; n < 8; n++)
#pragma unroll
        for (int c = 0; c < 4; c++) acc[n][c] = 0.0f;
#pragma unroll
    for (int ks = 0; ks < 4; ks++) {
        uint32_t ah[4], al[4];
        int wb = (rbase + g) * XW + qd + ks * 8;
        ah[0] = Xh[wb];          ah[1] = Xh[wb + 8 * XW];
        ah[2] = Xh[wb + 4];      ah[3] = Xh[wb + 8 * XW + 4];
        al[0] = Xl[wb];          al[1] = Xl[wb + 8 * XW];
        al[2] = Xl[wb + 4];      al[3] = Xl[wb + 8 * XW + 4];
        const uint2 *wrow = Wf + (m * 8 * 4 + ks) * 32 + lane;
#pragma unroll
        for (int n = 0; n < 8; n++) {
            uint2 F = wrow[n * 4 * 32];
            mma_f16(acc[n], ah, F.x, F.y);
            mma_f16(acc[n], al, F.x, F.y);
        }
    }
}

// ---------------- W prep (fp16, fragment order) + smax/denom zeroing ------
__global__ void prep_kernel(const float *__restrict__ Wq,
                            const float *__restrict__ Wk,
                            const float *__restrict__ Wv) {
    int t = blockIdx.x * blockDim.x + threadIdx.x;
    if (t < 3072) {
        int lane = t & 31;
        int ks = (t >> 5) & 3;
        int n = (t >> 7) & 7;
        int m = t >> 10;
        const float *W = (m == 0) ? Wq : (m == 1) ? Wk : Wv;
        int j = n * 8 + (lane >> 2);
        int k0 = 2 * (lane & 3) + 16 * ks;
        uint2 f;
        f.x = pack_h2(W[(k0 + 0) * 64 + j], W[(k0 + 1) * 64 + j]);
        f.y = pack_h2(W[(k0 + 8) * 64 + j], W[(k0 + 9) * 64 + j]);
        g_wfrag[t] = f;
    }
    if (t < NN * 4) {
        g_smax[t] = 0.0f;
        g_denom[t] = 0.0f;
    }
}

// ---------------- score pass: q,k projections + scores + smax ----------------
// 3 X tiles; k-lo restaged into q-lo buffer after q projection.
__global__ __launch_bounds__(256, 3) void score_kernel(
    const float *__restrict__ q, const float *__restrict__ k,
    const float *__restrict__ bq, const float *__restrict__ bk,
    const int *__restrict__ index) {
    extern __shared__ char smem[];
    uint32_t *Xqh = (uint32_t *)(smem + OFF_XQH);
    uint32_t *Xql = (uint32_t *)(smem + OFF_XQL);   // later: k-lo
    uint32_t *Xkh = (uint32_t *)(smem + OFF_XKH);
    uint2 *Wf = (uint2 *)(smem + OFF_WF_A);
    float *bs = (float *)(smem + OFF_BIAS_A);

    const int tid = threadIdx.x;
    const int w = tid >> 5;
    const int lane = tid & 31;
    const int g = lane >> 2;
    const int qd = lane & 3;
    const long gbase = (long)blockIdx.x * TE_S;

#pragma unroll
    for (int i = 0; i < 8; i++) Wf[tid + i * 256] = g_wfrag[tid + i * 256];
    if (tid < 64) {
        bs[tid] = bq[tid];
        bs[64 + tid] = bk[tid];
    }

    stageX2(q, gbase, Xqh, Xql, tid);
    stageX1(k, gbase, Xkh, tid);
    __syncthreads();

    float accQ[8][4];
    proj_tile2(Xqh, Xql, Wf, 0, w * 16, g, qd, lane, accQ);
    __syncthreads();                 // all warps done reading Xq tiles

    stageXlo(k, gbase, Xql, tid);    // k re-read is L1/L2 hot
    __syncthreads();

    float accK[8][4];
    proj_tile2(Xkh, Xql, Wf, 1, w * 16, g, qd, lane, accK);

    // bias add + per-head scores
#pragma unroll
    for (int n = 0; n < 8; n++) {
        int j0 = n * 8 + qd * 2;
        accQ[n][0] += bs[j0];      accQ[n][1] += bs[j0 + 1];
        accQ[n][2] += bs[j0];      accQ[n][3] += bs[j0 + 1];
        accK[n][0] += bs[64 + j0]; accK[n][1] += bs[64 + j0 + 1];
        accK[n][2] += bs[64 + j0]; accK[n][3] += bs[64 + j0 + 1];
    }

    float sc[2][4];
#pragma unroll
    for (int half = 0; half < 2; half++)
#pragma unroll
        for (int h = 0; h < 4; h++) {
            float p = 0.0f;
#pragma unroll
            for (int dn = 0; dn < 2; dn++) {
                int n = 2 * h + dn;
                p += accQ[n][half * 2] * accK[n][half * 2] +
                     accQ[n][half * 2 + 1] * accK[n][half * 2 + 1];
            }
            p += __shfl_xor_sync(FULL, p, 1);
            p += __shfl_xor_sync(FULL, p, 2);
            sc[half][h] = p;
        }

#pragma unroll
    for (int half = 0; half < 2; half++) {
        long e = gbase + w * 16 + half * 8 + g;
        float s = (qd & 2) ? ((qd & 1) ? sc[half][3] : sc[half][2])
                           : ((qd & 1) ? sc[half][1] : sc[half][0]);
        s *= 0.25f;
        g_score[e * 4 + qd] = s;

        // warp-aggregated atomicMax over contiguous same-index runs
        int nidx = index[e];
        float sm = s;
#pragma unroll
        for (int off = 4; off < 32; off <<= 1) {
            float o = __shfl_down_sync(FULL, sm, off);
            int no = __shfl_down_sync(FULL, nidx, off);
            if (lane + off < 32 && no == nidx) sm = fmaxf(sm, o);
        }
        int nprev = __shfl_up_sync(FULL, nidx, 4);
        bool leader = (g == 0) || (nprev != nidx);
        if (leader && sm > 0.0f)
            atomicMax((int *)&g_smax[nidx * 4 + qd], __float_as_int(sm));
    }
}

// ---------------- value pass: V projection (pure fp16) * attn -> out ------
__global__ __launch_bounds__(256, 4) void value_kernel(
    const float *__restrict__ v, const float *__restrict__ bv,
    const int *__restrict__ index, float *__restrict__ out) {
    extern __shared__ char smem[];
    uint32_t *X = (uint32_t *)(smem + OFF_XV);
    uint2 *Wf = (uint2 *)(smem + OFF_WF_B);
    float *bs = (float *)(smem + OFF_BIAS_B);

    const int tid = threadIdx.x;
    const int w = tid >> 5;
    const int lane = tid & 31;
    const int g = lane >> 2;
    const int qd = lane & 3;
    const long gbase = (long)blockIdx.x * TE_V;

#pragma unroll
    for (int i = 0; i < 4; i++)
        Wf[tid + i * 256] = g_wfrag[2048 + tid + i * 256];
    if (tid < 64) bs[tid] = bv[tid];

    stageX1(v, gbase, X, tid);

    // attn = exp(s - mx) / (denom_sum + exp(-mx)); fetch during staging
    const long e0 = gbase + w * 16 + g;   // rows e0, e0+8
    float att[2][4];
#pragma unroll
    for (int r = 0; r < 2; r++) {
        long e = e0 + r * 8;
        int n = index[e];
        float4 s = ((const float4 *)g_score)[e];
        float4 dn = ((const float4 *)g_denom)[n];
        float4 mx = ((const float4 *)g_smax)[n];
        att[r][0] = __fdividef(__expf(s.x - mx.x), dn.x + __expf(-mx.x));
        att[r][1] = __fdividef(__expf(s.y - mx.y), dn.y + __expf(-mx.y));
        att[r][2] = __fdividef(__expf(s.z - mx.z), dn.z + __expf(-mx.z));
        att[r][3] = __fdividef(__expf(s.w - mx.w), dn.w + __expf(-mx.w));
    }

    __syncthreads();

    float acc[8][4];
#pragma unroll
    for (int n = 0; n < 8; n++)
#pragma unroll
        for (int c = 0; c < 4; c++) acc[n][c] = 0.0f;
    const int rbase = w * 16;
#pragma unroll
    for (int ks = 0; ks < 4; ks++) {
        uint32_t a[4];
        int wb = (rbase + g) * XW + qd + ks * 8;
        a[0] = X[wb];          a[1] = X[wb + 8 * XW];
        a[2] = X[wb + 4];      a[3] = X[wb + 8 * XW + 4];
        const uint2 *wrow = Wf + ks * 32 + lane;
#pragma unroll
        for (int n = 0; n < 8; n++) {
            uint2 F = wrow[n * 4 * 32];
            mma_f16(acc[n], a, F.x, F.y);
        }
    }

#pragma unroll
    for (int n = 0; n < 8; n++) {
        int h = n >> 1;
        int j0 = n * 8 + qd * 2;
        float2 v0, v1;
        v0.x = att[0][h] * (acc[n][0] + bs[j0]);
        v0.y = att[0][h] * (acc[n][1] + bs[j0 + 1]);
        v1.x = att[1][h] * (acc[n][2] + bs[j0]);
        v1.y = att[1][h] * (acc[n][3] + bs[j0 + 1]);
        *(float2 *)(out + (size_t)e0 * 64 + j0) = v0;
        *(float2 *)(out + (size_t)(e0 + 8) * 64 + j0) = v1;
    }
}

// ---------------- ex: warp-aggregated denom accumulation ----------------
__global__ void ex_kernel(const int *__restrict__ index) {
    int e = blockIdx.x * blockDim.x + threadIdx.x;
    if (e >= EE) return;
    const int lane = threadIdx.x & 31;
    int n = index[e];
    float4 s = ((const float4 *)g_score)[e];
    float4 mx = ((const float4 *)g_smax)[n];
    float4 acc;
    acc.x = __expf(s.x - mx.x);
    acc.y = __expf(s.y - mx.y);
    acc.z = __expf(s.z - mx.z);
    acc.w = __expf(s.w - mx.w);

    // segmented suffix-reduce over contiguous same-n runs (index sorted)
#pragma unroll
    for (int off = 1; off < 32; off <<= 1) {
        int no = __shfl_down_sync(FULL, n, off);
        float ox = __shfl_down_sync(FULL, acc.x, off);
        float oy = __shfl_down_sync(FULL, acc.y, off);
        float oz = __shfl_down_sync(FULL, acc.z, off);
        float ow = __shfl_down_sync(FULL, acc.w, off);
        if (lane + off < 32 && no == n) {
            acc.x += ox; acc.y += oy; acc.z += oz; acc.w += ow;
        }
    }
    int nprev = __shfl_up_sync(FULL, n, 1);
    bool leader = (lane == 0) || (nprev != n);
    if (leader) {
        atomicAdd(&g_denom[n * 4 + 0], acc.x);
        atomicAdd(&g_denom[n * 4 + 1], acc.y);
        atomicAdd(&g_denom[n * 4 + 2], acc.z);
        atomicAdd(&g_denom[n * 4 + 3], acc.w);
    }
}

// ---------------- launcher ----------------
extern "C" void kernel_launch(void *const *d_in, const int *in_sizes, int n_in,
                              void *d_out, int out_size) {
    const float *q = (const float *)d_in[0];
    const float *k = (const float *)d_in[1];
    const float *v = (const float *)d_in[2];
    const float *Wq = (const float *)d_in[3];
    const float *bq = (const float *)d_in[4];
    const float *Wk = (const float *)d_in[5];
    const float *bk = (const float *)d_in[6];
    const float *Wv = (const float *)d_in[7];
    const float *bv = (const float *)d_in[8];
    const int *index = (const int *)d_in[9];
    float *out = (float *)d_out;

    cudaFuncSetAttribute(score_kernel, cudaFuncAttributeMaxDynamicSharedMemorySize,
                         SMEM_A);
    cudaFuncSetAttribute(value_kernel, cudaFuncAttributeMaxDynamicSharedMemorySize,
                         SMEM_B);

    prep_kernel<<<(NN * 4 + 255) / 256, 256>>>(Wq, Wk, Wv);
    score_kernel<<<NBLK_S, 256, SMEM_A>>>(q, k, bq, bk, index);
    ex_kernel<<<(EE + 255) / 256, 256>>>(index);
    value_kernel<<<NBLK_V, 256, SMEM_B>>>(v, bv, index, out);
}

// round 11
// speedup vs baseline: 1.2033x; 1.2033x over previous
#include <cuda_runtime.h>
#include <cuda_fp16.h>
#include <cstdint>

#define EE 800000
#define NN 50000
#define FULL 0xFFFFFFFFu

#define TE_S 128
#define NBLK_S (EE / TE_S)   // 6250
#define TE_V 128
#define NBLK_V (EE / TE_V)   // 6250

// ---------------- scratch (device globals; no allocation) ----------------
__device__ float g_score[(size_t)EE * 4];   // raw scores
__device__ float g_smax[NN * 4];
__device__ float g_denom[NN * 4];           // segment_sum(ex)
__device__ uint2 g_wfrag[3 * 8 * 4 * 32];   // [mat][n][ks][lane] = {wh0, wh1} fp16

// ---------------- smem layouts (bytes) ----------------
#define XW 36                                 // words per X row (64 fp16 + pad)
#define XTILE (128 * 144)
// score kernel: Xq_h, Xq_l, Xk_h (no k-lo), Wf(2 mats), bias
#define OFF_XQH 0
#define OFF_XQL (XTILE)
#define OFF_XKH (2 * XTILE)
#define OFF_WF_A (3 * XTILE)
#define OFF_BIAS_A (OFF_WF_A + 2048 * 8)
#define SMEM_A (OFF_BIAS_A + 512)             // 72.2 KB -> 3 blocks/SM
// value kernel: Xv (fp16 only), Wf(1 mat), bias
#define OFF_XV 0
#define OFF_WF_B (XTILE)
#define OFF_BIAS_B (OFF_WF_B + 1024 * 8)
#define SMEM_B (OFF_BIAS_B + 256)

// ---------------- helpers ----------------
__device__ __forceinline__ uint32_t pack_h2(float a, float b) {
    __half2 h = __floats2half2_rn(a, b);
    return *(uint32_t *)&h;
}

__device__ __forceinline__ void mma_f16(float c[4], const uint32_t a[4],
                                        uint32_t b0, uint32_t b1) {
    asm volatile(
        "mma.sync.aligned.m16n8k16.row.col.f32.f16.f16.f32 "
        "{%0,%1,%2,%3}, {%4,%5,%6,%7}, {%8,%9}, {%0,%1,%2,%3};"
        : "+f"(c[0]), "+f"(c[1]), "+f"(c[2]), "+f"(c[3])
        : "r"(a[0]), "r"(a[1]), "r"(a[2]), "r"(a[3]), "r"(b0), "r"(b1));
}

// stage 128-row X tile -> fp16 hi + lo smem tiles
__device__ __forceinline__ void stageX2(const float *__restrict__ gsrc, long gbase,
                                        uint32_t *Xh, uint32_t *Xl, int tid) {
#pragma unroll
    for (int it = 0; it < 8; it++) {
        int idx = tid + it * 256;            // over 2048 float4
        int row = idx >> 4, c4 = idx & 15;
        float4 x = ((const float4 *)(gsrc + (gbase + row) * 64))[c4];
        float hx = __half2float(__float2half_rn(x.x));
        float hy = __half2float(__float2half_rn(x.y));
        float hz = __half2float(__float2half_rn(x.z));
        float hw = __half2float(__float2half_rn(x.w));
        uint2 wh, wl;
        wh.x = pack_h2(hx, hy);
        wh.y = pack_h2(hz, hw);
        wl.x = pack_h2(x.x - hx, x.y - hy);
        wl.y = pack_h2(x.z - hz, x.w - hw);
        ((uint2 *)(Xh + row * XW))[c4] = wh;
        ((uint2 *)(Xl + row * XW))[c4] = wl;
    }
}

// stage 128-row X tile -> single fp16 smem tile
__device__ __forceinline__ void stageX1(const float *__restrict__ gsrc, long gbase,
                                        uint32_t *X, int tid) {
#pragma unroll
    for (int it = 0; it < 8; it++) {
        int idx = tid + it * 256;
        int row = idx >> 4, c4 = idx & 15;
        float4 x = ((const float4 *)(gsrc + (gbase + row) * 64))[c4];
        uint2 wrd;
        wrd.x = pack_h2(x.x, x.y);
        wrd.y = pack_h2(x.z, x.w);
        ((uint2 *)(X + row * XW))[c4] = wrd;
    }
}

// 16-edge m-tile projection, 2-term (x hi/lo): acc[8][4]
__device__ __forceinline__ void proj_tile2(const uint32_t *Xh, const uint32_t *Xl,
                                           const uint2 *Wf, int m, int rbase,
                                           int g, int qd, int lane, float acc[8][4]) {
#pragma unroll
    for (int n = 0; n < 8; n++)
#pragma unroll
        for (int c = 0; c < 4; c++) acc[n][c] = 0.0f;
#pragma unroll
    for (int ks = 0; ks < 4; ks++) {
        uint32_t ah[4], al[4];
        int wb = (rbase + g) * XW + qd + ks * 8;
        ah[0] = Xh[wb];          ah[1] = Xh[wb + 8 * XW];
        ah[2] = Xh[wb + 4];      ah[3] = Xh[wb + 8 * XW + 4];
        al[0] = Xl[wb];          al[1] = Xl[wb + 8 * XW];
        al[2] = Xl[wb + 4];      al[3] = Xl[wb + 8 * XW + 4];
        const uint2 *wrow = Wf + (m * 8 * 4 + ks) * 32 + lane;
#pragma unroll
        for (int n = 0; n < 8; n++) {
            uint2 F = wrow[n * 4 * 32];
            mma_f16(acc[n], ah, F.x, F.y);
            mma_f16(acc[n], al, F.x, F.y);
        }
    }
}

// 16-edge m-tile projection, 1-term (x fp16): acc[8][4]
__device__ __forceinline__ void proj_tile1(const uint32_t *X, const uint2 *Wf,
                                           int m, int rbase, int g, int qd,
                                           int lane, float acc[8][4]) {
#pragma unroll
    for (int n = 0; n < 8; n++)
#pragma unroll
        for (int c = 0; c < 4; c++) acc[n][c] = 0.0f;
#pragma unroll
    for (int ks = 0; ks < 4; ks++) {
        uint32_t a[4];
        int wb = (rbase + g) * XW + qd + ks * 8;
        a[0] = X[wb];          a[1] = X[wb + 8 * XW];
        a[2] = X[wb + 4];      a[3] = X[wb + 8 * XW + 4];
        const uint2 *wrow = Wf + (m * 8 * 4 + ks) * 32 + lane;
#pragma unroll
        for (int n = 0; n < 8; n++) {
            uint2 F = wrow[n * 4 * 32];
            mma_f16(acc[n], a, F.x, F.y);
        }
    }
}

// ---------------- W prep (fp16, fragment order) + smax/denom zeroing ------
__global__ void prep_kernel(const float *__restrict__ Wq,
                            const float *__restrict__ Wk,
                            const float *__restrict__ Wv) {
    int t = blockIdx.x * blockDim.x + threadIdx.x;
    if (t < 3072) {
        int lane = t & 31;
        int ks = (t >> 5) & 3;
        int n = (t >> 7) & 7;
        int m = t >> 10;
        const float *W = (m == 0) ? Wq : (m == 1) ? Wk : Wv;
        int j = n * 8 + (lane >> 2);
        int k0 = 2 * (lane & 3) + 16 * ks;
        uint2 f;
        f.x = pack_h2(W[(k0 + 0) * 64 + j], W[(k0 + 1) * 64 + j]);
        f.y = pack_h2(W[(k0 + 8) * 64 + j], W[(k0 + 9) * 64 + j]);
        g_wfrag[t] = f;
    }
    if (t < NN * 4) {
        g_smax[t] = 0.0f;
        g_denom[t] = 0.0f;
    }
}

// ---------------- score pass: q (2-term), k (1-term) + scores + smax ------
__global__ __launch_bounds__(256, 3) void score_kernel(
    const float *__restrict__ q, const float *__restrict__ k,
    const float *__restrict__ bq, const float *__restrict__ bk,
    const int *__restrict__ index) {
    extern __shared__ char smem[];
    uint32_t *Xqh = (uint32_t *)(smem + OFF_XQH);
    uint32_t *Xql = (uint32_t *)(smem + OFF_XQL);
    uint32_t *Xkh = (uint32_t *)(smem + OFF_XKH);
    uint2 *Wf = (uint2 *)(smem + OFF_WF_A);
    float *bs = (float *)(smem + OFF_BIAS_A);

    const int tid = threadIdx.x;
    const int w = tid >> 5;
    const int lane = tid & 31;
    const int g = lane >> 2;
    const int qd = lane & 3;
    const long gbase = (long)blockIdx.x * TE_S;

#pragma unroll
    for (int i = 0; i < 8; i++) Wf[tid + i * 256] = g_wfrag[tid + i * 256];
    if (tid < 64) {
        bs[tid] = bq[tid];
        bs[64 + tid] = bk[tid];
    }

    stageX2(q, gbase, Xqh, Xql, tid);
    stageX1(k, gbase, Xkh, tid);
    __syncthreads();

    float accQ[8][4], accK[8][4];
    proj_tile2(Xqh, Xql, Wf, 0, w * 16, g, qd, lane, accQ);
    proj_tile1(Xkh, Wf, 1, w * 16, g, qd, lane, accK);

    // bias add + per-head scores
#pragma unroll
    for (int n = 0; n < 8; n++) {
        int j0 = n * 8 + qd * 2;
        accQ[n][0] += bs[j0];      accQ[n][1] += bs[j0 + 1];
        accQ[n][2] += bs[j0];      accQ[n][3] += bs[j0 + 1];
        accK[n][0] += bs[64 + j0]; accK[n][1] += bs[64 + j0 + 1];
        accK[n][2] += bs[64 + j0]; accK[n][3] += bs[64 + j0 + 1];
    }

    float sc[2][4];
#pragma unroll
    for (int half = 0; half < 2; half++)
#pragma unroll
        for (int h = 0; h < 4; h++) {
            float p = 0.0f;
#pragma unroll
            for (int dn = 0; dn < 2; dn++) {
                int n = 2 * h + dn;
                p += accQ[n][half * 2] * accK[n][half * 2] +
                     accQ[n][half * 2 + 1] * accK[n][half * 2 + 1];
            }
            p += __shfl_xor_sync(FULL, p, 1);
            p += __shfl_xor_sync(FULL, p, 2);
            sc[half][h] = p;
        }

#pragma unroll
    for (int half = 0; half < 2; half++) {
        long e = gbase + w * 16 + half * 8 + g;
        float s = (qd & 2) ? ((qd & 1) ? sc[half][3] : sc[half][2])
                           : ((qd & 1) ? sc[half][1] : sc[half][0]);
        s *= 0.25f;
        g_score[e * 4 + qd] = s;

        // warp-aggregated atomicMax over contiguous same-index runs
        int nidx = index[e];
        float sm = s;
#pragma unroll
        for (int off = 4; off < 32; off <<= 1) {
            float o = __shfl_down_sync(FULL, sm, off);
            int no = __shfl_down_sync(FULL, nidx, off);
            if (lane + off < 32 && no == nidx) sm = fmaxf(sm, o);
        }
        int nprev = __shfl_up_sync(FULL, nidx, 4);
        bool leader = (g == 0) || (nprev != nidx);
        if (leader && sm > 0.0f)
            atomicMax((int *)&g_smax[nidx * 4 + qd], __float_as_int(sm));
    }
}

// ---------------- value pass: V projection (pure fp16) * attn -> out ------
__global__ __launch_bounds__(256, 4) void value_kernel(
    const float *__restrict__ v, const float *__restrict__ bv,
    const int *__restrict__ index, float *__restrict__ out) {
    extern __shared__ char smem[];
    uint32_t *X = (uint32_t *)(smem + OFF_XV);
    uint2 *Wf = (uint2 *)(smem + OFF_WF_B);
    float *bs = (float *)(smem + OFF_BIAS_B);

    const int tid = threadIdx.x;
    const int w = tid >> 5;
    const int lane = tid & 31;
    const int g = lane >> 2;
    const int qd = lane & 3;
    const long gbase = (long)blockIdx.x * TE_V;

#pragma unroll
    for (int i = 0; i < 4; i++)
        Wf[tid + i * 256] = g_wfrag[2048 + tid + i * 256];
    if (tid < 64) bs[tid] = bv[tid];

    stageX1(v, gbase, X, tid);

    // attn = exp(s - mx) / (denom_sum + exp(-mx)); fetch during staging
    const long e0 = gbase + w * 16 + g;   // rows e0, e0+8
    float att[2][4];
#pragma unroll
    for (int r = 0; r < 2; r++) {
        long e = e0 + r * 8;
        int n = index[e];
        float4 s = ((const float4 *)g_score)[e];
        float4 dn = ((const float4 *)g_denom)[n];
        float4 mx = ((const float4 *)g_smax)[n];
        att[r][0] = __fdividef(__expf(s.x - mx.x), dn.x + __expf(-mx.x));
        att[r][1] = __fdividef(__expf(s.y - mx.y), dn.y + __expf(-mx.y));
        att[r][2] = __fdividef(__expf(s.z - mx.z), dn.z + __expf(-mx.z));
        att[r][3] = __fdividef(__expf(s.w - mx.w), dn.w + __expf(-mx.w));
    }

    __syncthreads();

    float acc[8][4];
#pragma unroll
    for (int n = 0; n < 8; n++)
#pragma unroll
        for (int c = 0; c < 4; c++) acc[n][c] = 0.0f;
    const int rbase = w * 16;
#pragma unroll
    for (int ks = 0; ks < 4; ks++) {
        uint32_t a[4];
        int wb = (rbase + g) * XW + qd + ks * 8;
        a[0] = X[wb];          a[1] = X[wb + 8 * XW];
        a[2] = X[wb + 4];      a[3] = X[wb + 8 * XW + 4];
        const uint2 *wrow = Wf + ks * 32 + lane;
#pragma unroll
        for (int n = 0; n < 8; n++) {
            uint2 F = wrow[n * 4 * 32];
            mma_f16(acc[n], a, F.x, F.y);
        }
    }

#pragma unroll
    for (int n = 0; n < 8; n++) {
        int h = n >> 1;
        int j0 = n * 8 + qd * 2;
        float2 v0, v1;
        v0.x = att[0][h] * (acc[n][0] + bs[j0]);
        v0.y = att[0][h] * (acc[n][1] + bs[j0 + 1]);
        v1.x = att[1][h] * (acc[n][2] + bs[j0]);
        v1.y = att[1][h] * (acc[n][3] + bs[j0 + 1]);
        *(float2 *)(out + (size_t)e0 * 64 + j0) = v0;
        *(float2 *)(out + (size_t)(e0 + 8) * 64 + j0) = v1;
    }
}

// ---------------- ex: warp-aggregated denom accumulation ----------------
__global__ void ex_kernel(const int *__restrict__ index) {
    int e = blockIdx.x * blockDim.x + threadIdx.x;
    if (e >= EE) return;
    const int lane = threadIdx.x & 31;
    int n = index[e];
    float4 s = ((const float4 *)g_score)[e];
    float4 mx = ((const float4 *)g_smax)[n];
    float4 acc;
    acc.x = __expf(s.x - mx.x);
    acc.y = __expf(s.y - mx.y);
    acc.z = __expf(s.z - mx.z);
    acc.w = __expf(s.w - mx.w);

    // segmented suffix-reduce over contiguous same-n runs (index sorted)
#pragma unroll
    for (int off = 1; off < 32; off <<= 1) {
        int no = __shfl_down_sync(FULL, n, off);
        float ox = __shfl_down_sync(FULL, acc.x, off);
        float oy = __shfl_down_sync(FULL, acc.y, off);
        float oz = __shfl_down_sync(FULL, acc.z, off);
        float ow = __shfl_down_sync(FULL, acc.w, off);
        if (lane + off < 32 && no == n) {
            acc.x += ox; acc.y += oy; acc.z += oz; acc.w += ow;
        }
    }
    int nprev = __shfl_up_sync(FULL, n, 1);
    bool leader = (lane == 0) || (nprev != n);
    if (leader) {
        atomicAdd(&g_denom[n * 4 + 0], acc.x);
        atomicAdd(&g_denom[n * 4 + 1], acc.y);
        atomicAdd(&g_denom[n * 4 + 2], acc.z);
        atomicAdd(&g_denom[n * 4 + 3], acc.w);
    }
}

// ---------------- launcher ----------------
extern "C" void kernel_launch(void *const *d_in, const int *in_sizes, int n_in,
                              void *d_out, int out_size) {
    const float *q = (const float *)d_in[0];
    const float *k = (const float *)d_in[1];
    const float *v = (const float *)d_in[2];
    const float *Wq = (const float *)d_in[3];
    const float *bq = (const float *)d_in[4];
    const float *Wk = (const float *)d_in[5];
    const float *bk = (const float *)d_in[6];
    const float *Wv = (const float *)d_in[7];
    const float *bv = (const float *)d_in[8];
    const int *index = (const int *)d_in[9];
    float *out = (float *)d_out;

    cudaFuncSetAttribute(score_kernel, cudaFuncAttributeMaxDynamicSharedMemorySize,
                         SMEM_A);
    cudaFuncSetAttribute(value_kernel, cudaFuncAttributeMaxDynamicSharedMemorySize,
                         SMEM_B);

    prep_kernel<<<(NN * 4 + 255) / 256, 256>>>(Wq, Wk, Wv);
    score_kernel<<<NBLK_S, 256, SMEM_A>>>(q, k, bq, bk, index);
    ex_kernel<<<(EE + 255) / 256, 256>>>(index);
    value_kernel<<<NBLK_V, 256, SMEM_B>>>(v, bv, index, out);
}

// round 12
// speedup vs baseline: 1.2682x; 1.0539x over previous
#include <cuda_runtime.h>
#include <cuda_fp16.h>
#include <cstdint>

#define EE 800000
#define NN 50000
#define FULL 0xFFFFFFFFu

#define TE_S 128
#define NBLK_S (EE / TE_S)   // 6250
#define TE_V 128
#define NBLK_V (EE / TE_V)   // 6250

// ---------------- scratch (device globals; no allocation) ----------------
__device__ float g_score[(size_t)EE * 4];   // exp(score) per edge/head
__device__ float g_denom[NN * 4];           // segment_sum(exp(score))
__device__ uint2 g_wfrag[3 * 8 * 4 * 32];   // [mat][n][ks][lane] = {wh0, wh1} fp16

// ---------------- smem layouts (bytes) ----------------
#define XW 36                                 // words per X row (64 fp16 + pad)
#define XTILE (128 * 144)
// score kernel: Xq_h, Xq_l, Xk_h, Wf(2 mats), bias
#define OFF_XQH 0
#define OFF_XQL (XTILE)
#define OFF_XKH (2 * XTILE)
#define OFF_WF_A (3 * XTILE)
#define OFF_BIAS_A (OFF_WF_A + 2048 * 8)
#define SMEM_A (OFF_BIAS_A + 512)             // 72.2 KB -> 3 blocks/SM
// value kernel: Xv (fp16 only), Wf(1 mat), bias
#define OFF_XV 0
#define OFF_WF_B (XTILE)
#define OFF_BIAS_B (OFF_WF_B + 1024 * 8)
#define SMEM_B (OFF_BIAS_B + 256)

// ---------------- helpers ----------------
__device__ __forceinline__ uint32_t pack_h2(float a, float b) {
    __half2 h = __floats2half2_rn(a, b);
    return *(uint32_t *)&h;
}

__device__ __forceinline__ void mma_f16(float c[4], const uint32_t a[4],
                                        uint32_t b0, uint32_t b1) {
    asm volatile(
        "mma.sync.aligned.m16n8k16.row.col.f32.f16.f16.f32 "
        "{%0,%1,%2,%3}, {%4,%5,%6,%7}, {%8,%9}, {%0,%1,%2,%3};"
        : "+f"(c[0]), "+f"(c[1]), "+f"(c[2]), "+f"(c[3])
        : "r"(a[0]), "r"(a[1]), "r"(a[2]), "r"(a[3]), "r"(b0), "r"(b1));
}

// stage 128-row X tile -> fp16 hi + lo smem tiles
__device__ __forceinline__ void stageX2(const float *__restrict__ gsrc, long gbase,
                                        uint32_t *Xh, uint32_t *Xl, int tid) {
#pragma unroll
    for (int it = 0; it < 8; it++) {
        int idx = tid + it * 256;            // over 2048 float4
        int row = idx >> 4, c4 = idx & 15;
        float4 x = ((const float4 *)(gsrc + (gbase + row) * 64))[c4];
        float hx = __half2float(__float2half_rn(x.x));
        float hy = __half2float(__float2half_rn(x.y));
        float hz = __half2float(__float2half_rn(x.z));
        float hw = __half2float(__float2half_rn(x.w));
        uint2 wh, wl;
        wh.x = pack_h2(hx, hy);
        wh.y = pack_h2(hz, hw);
        wl.x = pack_h2(x.x - hx, x.y - hy);
        wl.y = pack_h2(x.z - hz, x.w - hw);
        ((uint2 *)(Xh + row * XW))[c4] = wh;
        ((uint2 *)(Xl + row * XW))[c4] = wl;
    }
}

// stage 128-row X tile -> single fp16 smem tile
__device__ __forceinline__ void stageX1(const float *__restrict__ gsrc, long gbase,
                                        uint32_t *X, int tid) {
#pragma unroll
    for (int it = 0; it < 8; it++) {
        int idx = tid + it * 256;
        int row = idx >> 4, c4 = idx & 15;
        float4 x = ((const float4 *)(gsrc + (gbase + row) * 64))[c4];
        uint2 wrd;
        wrd.x = pack_h2(x.x, x.y);
        wrd.y = pack_h2(x.z, x.w);
        ((uint2 *)(X + row * XW))[c4] = wrd;
    }
}

// 16-edge m-tile projection, 2-term (x hi/lo): acc[8][4]
__device__ __forceinline__ void proj_tile2(const uint32_t *Xh, const uint32_t *Xl,
                                           const uint2 *Wf, int m, int rbase,
                                           int g, int qd, int lane, float acc[8][4]) {
#pragma unroll
    for (int n = 0; n < 8; n++)
#pragma unroll
        for (int c = 0; c < 4; c++) acc[n][c] = 0.0f;
#pragma unroll
    for (int ks = 0; ks < 4; ks++) {
        uint32_t ah[4], al[4];
        int wb = (rbase + g) * XW + qd + ks * 8;
        ah[0] = Xh[wb];          ah[1] = Xh[wb + 8 * XW];
        ah[2] = Xh[wb + 4];      ah[3] = Xh[wb + 8 * XW + 4];
        al[0] = Xl[wb];          al[1] = Xl[wb + 8 * XW];
        al[2] = Xl[wb + 4];      al[3] = Xl[wb + 8 * XW + 4];
        const uint2 *wrow = Wf + (m * 8 * 4 + ks) * 32 + lane;
#pragma unroll
        for (int n = 0; n < 8; n++) {
            uint2 F = wrow[n * 4 * 32];
            mma_f16(acc[n], ah, F.x, F.y);
            mma_f16(acc[n], al, F.x, F.y);
        }
    }
}

// 16-edge m-tile projection, 1-term (x fp16): acc[8][4]
__device__ __forceinline__ void proj_tile1(const uint32_t *X, const uint2 *Wf,
                                           int m, int rbase, int g, int qd,
                                           int lane, float acc[8][4]) {
#pragma unroll
    for (int n = 0; n < 8; n++)
#pragma unroll
        for (int c = 0; c < 4; c++) acc[n][c] = 0.0f;
#pragma unroll
    for (int ks = 0; ks < 4; ks++) {
        uint32_t a[4];
        int wb = (rbase + g) * XW + qd + ks * 8;
        a[0] = X[wb];          a[1] = X[wb + 8 * XW];
        a[2] = X[wb + 4];      a[3] = X[wb + 8 * XW + 4];
        const uint2 *wrow = Wf + (m * 8 * 4 + ks) * 32 + lane;
#pragma unroll
        for (int n = 0; n < 8; n++) {
            uint2 F = wrow[n * 4 * 32];
            mma_f16(acc[n], a, F.x, F.y);
        }
    }
}

// ---------------- W prep (fp16, fragment order) + denom zeroing ----------
__global__ void prep_kernel(const float *__restrict__ Wq,
                            const float *__restrict__ Wk,
                            const float *__restrict__ Wv) {
    int t = blockIdx.x * blockDim.x + threadIdx.x;
    if (t < 3072) {
        int lane = t & 31;
        int ks = (t >> 5) & 3;
        int n = (t >> 7) & 7;
        int m = t >> 10;
        const float *W = (m == 0) ? Wq : (m == 1) ? Wk : Wv;
        int j = n * 8 + (lane >> 2);
        int k0 = 2 * (lane & 3) + 16 * ks;
        uint2 f;
        f.x = pack_h2(W[(k0 + 0) * 64 + j], W[(k0 + 1) * 64 + j]);
        f.y = pack_h2(W[(k0 + 8) * 64 + j], W[(k0 + 9) * 64 + j]);
        g_wfrag[t] = f;
    }
    if (t < NN * 4) g_denom[t] = 0.0f;
}

// ---------------- score pass: q (2-term), k (1-term) -> exp + denom ------
// attn softmax identity: exp(s-m)/(sum exp(s'-m) + exp(-m)) == exp(s)/(sum exp(s') + 1)
__global__ __launch_bounds__(256, 3) void score_kernel(
    const float *__restrict__ q, const float *__restrict__ k,
    const float *__restrict__ bq, const float *__restrict__ bk,
    const int *__restrict__ index) {
    extern __shared__ char smem[];
    uint32_t *Xqh = (uint32_t *)(smem + OFF_XQH);
    uint32_t *Xql = (uint32_t *)(smem + OFF_XQL);
    uint32_t *Xkh = (uint32_t *)(smem + OFF_XKH);
    uint2 *Wf = (uint2 *)(smem + OFF_WF_A);
    float *bs = (float *)(smem + OFF_BIAS_A);

    const int tid = threadIdx.x;
    const int w = tid >> 5;
    const int lane = tid & 31;
    const int g = lane >> 2;
    const int qd = lane & 3;
    const long gbase = (long)blockIdx.x * TE_S;

#pragma unroll
    for (int i = 0; i < 8; i++) Wf[tid + i * 256] = g_wfrag[tid + i * 256];
    if (tid < 64) {
        bs[tid] = bq[tid];
        bs[64 + tid] = bk[tid];
    }

    stageX2(q, gbase, Xqh, Xql, tid);
    stageX1(k, gbase, Xkh, tid);
    __syncthreads();

    float accQ[8][4], accK[8][4];
    proj_tile2(Xqh, Xql, Wf, 0, w * 16, g, qd, lane, accQ);
    proj_tile1(Xkh, Wf, 1, w * 16, g, qd, lane, accK);

    // bias add + per-head scores
#pragma unroll
    for (int n = 0; n < 8; n++) {
        int j0 = n * 8 + qd * 2;
        accQ[n][0] += bs[j0];      accQ[n][1] += bs[j0 + 1];
        accQ[n][2] += bs[j0];      accQ[n][3] += bs[j0 + 1];
        accK[n][0] += bs[64 + j0]; accK[n][1] += bs[64 + j0 + 1];
        accK[n][2] += bs[64 + j0]; accK[n][3] += bs[64 + j0 + 1];
    }

    float sc[2][4];
#pragma unroll
    for (int half = 0; half < 2; half++)
#pragma unroll
        for (int h = 0; h < 4; h++) {
            float p = 0.0f;
#pragma unroll
            for (int dn = 0; dn < 2; dn++) {
                int n = 2 * h + dn;
                p += accQ[n][half * 2] * accK[n][half * 2] +
                     accQ[n][half * 2 + 1] * accK[n][half * 2 + 1];
            }
            p += __shfl_xor_sync(FULL, p, 1);
            p += __shfl_xor_sync(FULL, p, 2);
            sc[half][h] = p;
        }

#pragma unroll
    for (int half = 0; half < 2; half++) {
        long e = gbase + w * 16 + half * 8 + g;
        float s = (qd & 2) ? ((qd & 1) ? sc[half][3] : sc[half][2])
                           : ((qd & 1) ? sc[half][1] : sc[half][0]);
        float exv = __expf(s * 0.25f);
        g_score[e * 4 + qd] = exv;

        // warp-aggregated segmented atomicAdd over contiguous same-index runs
        // (lanes stride 4 share qd; edges g=0..7 are consecutive; index sorted)
        int nidx = index[e];
        float sum = exv;
#pragma unroll
        for (int off = 4; off < 32; off <<= 1) {
            float o = __shfl_down_sync(FULL, sum, off);
            int no = __shfl_down_sync(FULL, nidx, off);
            if (lane + off < 32 && no == nidx) sum += o;
        }
        int nprev = __shfl_up_sync(FULL, nidx, 4);
        bool leader = (g == 0) || (nprev != nidx);
        if (leader)
            atomicAdd(&g_denom[nidx * 4 + qd], sum);
    }
}

// ---------------- value pass: V projection (pure fp16) * attn -> out ------
__global__ __launch_bounds__(256, 4) void value_kernel(
    const float *__restrict__ v, const float *__restrict__ bv,
    const int *__restrict__ index, float *__restrict__ out) {
    extern __shared__ char smem[];
    uint32_t *X = (uint32_t *)(smem + OFF_XV);
    uint2 *Wf = (uint2 *)(smem + OFF_WF_B);
    float *bs = (float *)(smem + OFF_BIAS_B);

    const int tid = threadIdx.x;
    const int w = tid >> 5;
    const int lane = tid & 31;
    const int g = lane >> 2;
    const int qd = lane & 3;
    const long gbase = (long)blockIdx.x * TE_V;

#pragma unroll
    for (int i = 0; i < 4; i++)
        Wf[tid + i * 256] = g_wfrag[2048 + tid + i * 256];
    if (tid < 64) bs[tid] = bv[tid];

    stageX1(v, gbase, X, tid);

    // attn = ex / (denom_sum + 1); fetch during staging
    const long e0 = gbase + w * 16 + g;   // rows e0, e0+8
    float att[2][4];
#pragma unroll
    for (int r = 0; r < 2; r++) {
        long e = e0 + r * 8;
        int n = index[e];
        float4 ex = ((const float4 *)g_score)[e];
        float4 dn = ((const float4 *)g_denom)[n];
        att[r][0] = __fdividef(ex.x, dn.x + 1.0f);
        att[r][1] = __fdividef(ex.y, dn.y + 1.0f);
        att[r][2] = __fdividef(ex.z, dn.z + 1.0f);
        att[r][3] = __fdividef(ex.w, dn.w + 1.0f);
    }

    __syncthreads();

    float acc[8][4];
#pragma unroll
    for (int n = 0; n < 8; n++)
#pragma unroll
        for (int c = 0; c < 4; c++) acc[n][c] = 0.0f;
    const int rbase = w * 16;
#pragma unroll
    for (int ks = 0; ks < 4; ks++) {
        uint32_t a[4];
        int wb = (rbase + g) * XW + qd + ks * 8;
        a[0] = X[wb];          a[1] = X[wb + 8 * XW];
        a[2] = X[wb + 4];      a[3] = X[wb + 8 * XW + 4];
        const uint2 *wrow = Wf + ks * 32 + lane;
#pragma unroll
        for (int n = 0; n < 8; n++) {
            uint2 F = wrow[n * 4 * 32];
            mma_f16(acc[n], a, F.x, F.y);
        }
    }

#pragma unroll
    for (int n = 0; n < 8; n++) {
        int h = n >> 1;
        int j0 = n * 8 + qd * 2;
        float2 v0, v1;
        v0.x = att[0][h] * (acc[n][0] + bs[j0]);
        v0.y = att[0][h] * (acc[n][1] + bs[j0 + 1]);
        v1.x = att[1][h] * (acc[n][2] + bs[j0]);
        v1.y = att[1][h] * (acc[n][3] + bs[j0 + 1]);
        *(float2 *)(out + (size_t)e0 * 64 + j0) = v0;
        *(float2 *)(out + (size_t)(e0 + 8) * 64 + j0) = v1;
    }
}

// ---------------- launcher ----------------
extern "C" void kernel_launch(void *const *d_in, const int *in_sizes, int n_in,
                              void *d_out, int out_size) {
    const float *q = (const float *)d_in[0];
    const float *k = (const float *)d_in[1];
    const float *v = (const float *)d_in[2];
    const float *Wq = (const float *)d_in[3];
    const float *bq = (const float *)d_in[4];
    const float *Wk = (const float *)d_in[5];
    const float *bk = (const float *)d_in[6];
    const float *Wv = (const float *)d_in[7];
    const float *bv = (const float *)d_in[8];
    const int *index = (const int *)d_in[9];
    float *out = (float *)d_out;

    cudaFuncSetAttribute(score_kernel, cudaFuncAttributeMaxDynamicSharedMemorySize,
                         SMEM_A);
    cudaFuncSetAttribute(value_kernel, cudaFuncAttributeMaxDynamicSharedMemorySize,
                         SMEM_B);

    prep_kernel<<<(NN * 4 + 255) / 256, 256>>>(Wq, Wk, Wv);
    score_kernel<<<NBLK_S, 256, SMEM_A>>>(q, k, bq, bk, index);
    value_kernel<<<NBLK_V, 256, SMEM_B>>>(v, bv, index, out);
}

// round 13
// speedup vs baseline: 1.4455x; 1.1398x over previous
#include <cuda_runtime.h>
#include <cuda_fp16.h>
#include <cstdint>

#define EE 800000
#define NN 50000
#define FULL 0xFFFFFFFFu

#define TE_S 128
#define NBLK_S (EE / TE_S)   // 6250
#define TE_V 128
#define NBLK_V (EE / TE_V)   // 6250

// ---------------- scratch (device globals; no allocation) ----------------
__device__ float g_score[(size_t)EE * 4];   // exp(score) per edge/head
__device__ float g_denom[NN * 4];           // segment_sum(exp(score))
__device__ uint2 g_wfrag[3 * 8 * 4 * 32];   // [mat][n][ks][lane] = {wh0, wh1} fp16

// ---------------- smem layouts (bytes) ----------------
#define XW 36                                 // words per X row (64 fp16 + pad)
#define XTILE (128 * 144)
// score kernel: Xq, Xk (fp16 only), Wf(2 mats), bias
#define OFF_XQ 0
#define OFF_XK (XTILE)
#define OFF_WF_A (2 * XTILE)
#define OFF_BIAS_A (OFF_WF_A + 2048 * 8)
#define SMEM_A (OFF_BIAS_A + 512)             // 53.8 KB
// value kernel: Xv (fp16 only), Wf(1 mat), bias
#define OFF_XV 0
#define OFF_WF_B (XTILE)
#define OFF_BIAS_B (OFF_WF_B + 1024 * 8)
#define SMEM_B (OFF_BIAS_B + 256)

// ---------------- helpers ----------------
__device__ __forceinline__ uint32_t pack_h2(float a, float b) {
    __half2 h = __floats2half2_rn(a, b);
    return *(uint32_t *)&h;
}

__device__ __forceinline__ void mma_f16(float c[4], const uint32_t a[4],
                                        uint32_t b0, uint32_t b1) {
    asm volatile(
        "mma.sync.aligned.m16n8k16.row.col.f32.f16.f16.f32 "
        "{%0,%1,%2,%3}, {%4,%5,%6,%7}, {%8,%9}, {%0,%1,%2,%3};"
        : "+f"(c[0]), "+f"(c[1]), "+f"(c[2]), "+f"(c[3])
        : "r"(a[0]), "r"(a[1]), "r"(a[2]), "r"(a[3]), "r"(b0), "r"(b1));
}

// stage 128-row X tile -> single fp16 smem tile
__device__ __forceinline__ void stageX1(const float *__restrict__ gsrc, long gbase,
                                        uint32_t *X, int tid) {
#pragma unroll
    for (int it = 0; it < 8; it++) {
        int idx = tid + it * 256;
        int row = idx >> 4, c4 = idx & 15;
        float4 x = ((const float4 *)(gsrc + (gbase + row) * 64))[c4];
        uint2 wrd;
        wrd.x = pack_h2(x.x, x.y);
        wrd.y = pack_h2(x.z, x.w);
        ((uint2 *)(X + row * XW))[c4] = wrd;
    }
}

// 16-edge m-tile projection, 1-term (x fp16): acc[8][4]
__device__ __forceinline__ void proj_tile1(const uint32_t *X, const uint2 *Wf,
                                           int m, int rbase, int g, int qd,
                                           int lane, float acc[8][4]) {
#pragma unroll
    for (int n = 0; n < 8; n++)
#pragma unroll
        for (int c = 0; c < 4; c++) acc[n][c] = 0.0f;
#pragma unroll
    for (int ks = 0; ks < 4; ks++) {
        uint32_t a[4];
        int wb = (rbase + g) * XW + qd + ks * 8;
        a[0] = X[wb];          a[1] = X[wb + 8 * XW];
        a[2] = X[wb + 4];      a[3] = X[wb + 8 * XW + 4];
        const uint2 *wrow = Wf + (m * 8 * 4 + ks) * 32 + lane;
#pragma unroll
        for (int n = 0; n < 8; n++) {
            uint2 F = wrow[n * 4 * 32];
            mma_f16(acc[n], a, F.x, F.y);
        }
    }
}

// ---------------- W prep (fp16, fragment order) + denom zeroing ----------
__global__ void prep_kernel(const float *__restrict__ Wq,
                            const float *__restrict__ Wk,
                            const float *__restrict__ Wv) {
    int t = blockIdx.x * blockDim.x + threadIdx.x;
    if (t < 3072) {
        int lane = t & 31;
        int ks = (t >> 5) & 3;
        int n = (t >> 7) & 7;
        int m = t >> 10;
        const float *W = (m == 0) ? Wq : (m == 1) ? Wk : Wv;
        int j = n * 8 + (lane >> 2);
        int k0 = 2 * (lane & 3) + 16 * ks;
        uint2 f;
        f.x = pack_h2(W[(k0 + 0) * 64 + j], W[(k0 + 1) * 64 + j]);
        f.y = pack_h2(W[(k0 + 8) * 64 + j], W[(k0 + 9) * 64 + j]);
        g_wfrag[t] = f;
    }
    if (t < NN * 4) g_denom[t] = 0.0f;
}

// ---------------- score pass: q,k (1-term fp16) -> exp + denom ------------
// softmax identity: exp(s-m)/(sum exp(s'-m) + exp(-m)) == exp(s)/(sum exp(s') + 1)
__global__ __launch_bounds__(256, 3) void score_kernel(
    const float *__restrict__ q, const float *__restrict__ k,
    const float *__restrict__ bq, const float *__restrict__ bk,
    const int *__restrict__ index) {
    extern __shared__ char smem[];
    uint32_t *Xq = (uint32_t *)(smem + OFF_XQ);
    uint32_t *Xk = (uint32_t *)(smem + OFF_XK);
    uint2 *Wf = (uint2 *)(smem + OFF_WF_A);
    float *bs = (float *)(smem + OFF_BIAS_A);

    const int tid = threadIdx.x;
    const int w = tid >> 5;
    const int lane = tid & 31;
    const int g = lane >> 2;
    const int qd = lane & 3;
    const long gbase = (long)blockIdx.x * TE_S;

#pragma unroll
    for (int i = 0; i < 8; i++) Wf[tid + i * 256] = g_wfrag[tid + i * 256];
    if (tid < 64) {
        bs[tid] = bq[tid];
        bs[64 + tid] = bk[tid];
    }

    stageX1(q, gbase, Xq, tid);
    stageX1(k, gbase, Xk, tid);
    __syncthreads();

    float accQ[8][4], accK[8][4];
    proj_tile1(Xq, Wf, 0, w * 16, g, qd, lane, accQ);
    proj_tile1(Xk, Wf, 1, w * 16, g, qd, lane, accK);

    // bias add + per-head scores
#pragma unroll
    for (int n = 0; n < 8; n++) {
        int j0 = n * 8 + qd * 2;
        accQ[n][0] += bs[j0];      accQ[n][1] += bs[j0 + 1];
        accQ[n][2] += bs[j0];      accQ[n][3] += bs[j0 + 1];
        accK[n][0] += bs[64 + j0]; accK[n][1] += bs[64 + j0 + 1];
        accK[n][2] += bs[64 + j0]; accK[n][3] += bs[64 + j0 + 1];
    }

    float sc[2][4];
#pragma unroll
    for (int half = 0; half < 2; half++)
#pragma unroll
        for (int h = 0; h < 4; h++) {
            float p = 0.0f;
#pragma unroll
            for (int dn = 0; dn < 2; dn++) {
                int n = 2 * h + dn;
                p += accQ[n][half * 2] * accK[n][half * 2] +
                     accQ[n][half * 2 + 1] * accK[n][half * 2 + 1];
            }
            p += __shfl_xor_sync(FULL, p, 1);
            p += __shfl_xor_sync(FULL, p, 2);
            sc[half][h] = p;
        }

#pragma unroll
    for (int half = 0; half < 2; half++) {
        long e = gbase + w * 16 + half * 8 + g;
        float s = (qd & 2) ? ((qd & 1) ? sc[half][3] : sc[half][2])
                           : ((qd & 1) ? sc[half][1] : sc[half][0]);
        float exv = __expf(s * 0.25f);
        g_score[e * 4 + qd] = exv;

        // warp-aggregated segmented atomicAdd over contiguous same-index runs
        int nidx = index[e];
        float sum = exv;
#pragma unroll
        for (int off = 4; off < 32; off <<= 1) {
            float o = __shfl_down_sync(FULL, sum, off);
            int no = __shfl_down_sync(FULL, nidx, off);
            if (lane + off < 32 && no == nidx) sum += o;
        }
        int nprev = __shfl_up_sync(FULL, nidx, 4);
        bool leader = (g == 0) || (nprev != nidx);
        if (leader)
            atomicAdd(&g_denom[nidx * 4 + qd], sum);
    }
}

// ---------------- value pass: V projection (pure fp16) * attn -> out ------
__global__ __launch_bounds__(256, 4) void value_kernel(
    const float *__restrict__ v, const float *__restrict__ bv,
    const int *__restrict__ index, float *__restrict__ out) {
    extern __shared__ char smem[];
    uint32_t *X = (uint32_t *)(smem + OFF_XV);
    uint2 *Wf = (uint2 *)(smem + OFF_WF_B);
    float *bs = (float *)(smem + OFF_BIAS_B);

    const int tid = threadIdx.x;
    const int w = tid >> 5;
    const int lane = tid & 31;
    const int g = lane >> 2;
    const int qd = lane & 3;
    const long gbase = (long)blockIdx.x * TE_V;

#pragma unroll
    for (int i = 0; i < 4; i++)
        Wf[tid + i * 256] = g_wfrag[2048 + tid + i * 256];
    if (tid < 64) bs[tid] = bv[tid];

    stageX1(v, gbase, X, tid);

    // attn = ex / (denom_sum + 1); fetch during staging
    const long e0 = gbase + w * 16 + g;   // rows e0, e0+8
    float att[2][4];
#pragma unroll
    for (int r = 0; r < 2; r++) {
        long e = e0 + r * 8;
        int n = index[e];
        float4 ex = ((const float4 *)g_score)[e];
        float4 dn = ((const float4 *)g_denom)[n];
        att[r][0] = __fdividef(ex.x, dn.x + 1.0f);
        att[r][1] = __fdividef(ex.y, dn.y + 1.0f);
        att[r][2] = __fdividef(ex.z, dn.z + 1.0f);
        att[r][3] = __fdividef(ex.w, dn.w + 1.0f);
    }

    __syncthreads();

    float acc[8][4];
#pragma unroll
    for (int n = 0; n < 8; n++)
#pragma unroll
        for (int c = 0; c < 4; c++) acc[n][c] = 0.0f;
    const int rbase = w * 16;
#pragma unroll
    for (int ks = 0; ks < 4; ks++) {
        uint32_t a[4];
        int wb = (rbase + g) * XW + qd + ks * 8;
        a[0] = X[wb];          a[1] = X[wb + 8 * XW];
        a[2] = X[wb + 4];      a[3] = X[wb + 8 * XW + 4];
        const uint2 *wrow = Wf + ks * 32 + lane;
#pragma unroll
        for (int n = 0; n < 8; n++) {
            uint2 F = wrow[n * 4 * 32];
            mma_f16(acc[n], a, F.x, F.y);
        }
    }

#pragma unroll
    for (int n = 0; n < 8; n++) {
        int h = n >> 1;
        int j0 = n * 8 + qd * 2;
        float2 v0, v1;
        v0.x = att[0][h] * (acc[n][0] + bs[j0]);
        v0.y = att[0][h] * (acc[n][1] + bs[j0 + 1]);
        v1.x = att[1][h] * (acc[n][2] + bs[j0]);
        v1.y = att[1][h] * (acc[n][3] + bs[j0 + 1]);
        *(float2 *)(out + (size_t)e0 * 64 + j0) = v0;
        *(float2 *)(out + (size_t)(e0 + 8) * 64 + j0) = v1;
    }
}

// ---------------- launcher ----------------
extern "C" void kernel_launch(void *const *d_in, const int *in_sizes, int n_in,
                              void *d_out, int out_size) {
    const float *q = (const float *)d_in[0];
    const float *k = (const float *)d_in[1];
    const float *v = (const float *)d_in[2];
    const float *Wq = (const float *)d_in[3];
    const float *bq = (const float *)d_in[4];
    const float *Wk = (const float *)d_in[5];
    const float *bk = (const float *)d_in[6];
    const float *Wv = (const float *)d_in[7];
    const float *bv = (const float *)d_in[8];
    const int *index = (const int *)d_in[9];
    float *out = (float *)d_out;

    cudaFuncSetAttribute(score_kernel, cudaFuncAttributeMaxDynamicSharedMemorySize,
                         SMEM_A);
    cudaFuncSetAttribute(value_kernel, cudaFuncAttributeMaxDynamicSharedMemorySize,
                         SMEM_B);

    prep_kernel<<<(NN * 4 + 255) / 256, 256>>>(Wq, Wk, Wv);
    score_kernel<<<NBLK_S, 256, SMEM_A>>>(q, k, bq, bk, index);
    value_kernel<<<NBLK_V, 256, SMEM_B>>>(v, bv, index, out);
}